// round 2
// baseline (speedup 1.0000x reference)
#include <cuda_runtime.h>

#define BATCH 4
#define SEQ   4096
#define NEMB  1024
#define HD    128
#define BM    64
#define BN    64
#define PBK   32

// Scratch (device globals: allocation-free per harness rules)
__device__ float g_q[BATCH * SEQ * HD];
__device__ float g_k[BATCH * SEQ * HD];
__device__ float g_v[BATCH * SEQ * HD];

// ---------------------------------------------------------------------------
// QKV projection: out[m][n] = sum_k x[m][k] * W[k][n];  M=16384, K=1024, N=128
// grid = (M/BM, 3)  (z selects Wq/Wk/Wv), 256 threads, 4x8 micro-tile
// ---------------------------------------------------------------------------
__global__ __launch_bounds__(256, 2) void proj_kernel(
    const float* __restrict__ x,
    const float* __restrict__ Wq,
    const float* __restrict__ Wk,
    const float* __restrict__ Wv)
{
    __shared__ float xs[BM][PBK + 4];    // stride 36 floats (16B-aligned rows)
    __shared__ float ws[PBK][HD + 4];    // stride 132 floats

    const int which = blockIdx.y;
    const float* __restrict__ Wp = (which == 0) ? Wq : (which == 1) ? Wk : Wv;
    float* __restrict__ outp     = (which == 0) ? g_q : (which == 1) ? g_k : g_v;

    const int m0  = blockIdx.x * BM;
    const int tid = threadIdx.x;
    const int tx  = tid & 15, ty = tid >> 4;

    float acc[4][8];
#pragma unroll
    for (int i = 0; i < 4; i++)
#pragma unroll
        for (int j = 0; j < 8; j++) acc[i][j] = 0.f;

    for (int k0 = 0; k0 < NEMB; k0 += PBK) {
        // x tile 64x32 = 512 float4
#pragma unroll
        for (int i = 0; i < 2; i++) {
            int idx = tid + i * 256;
            int r = idx >> 3, c4 = idx & 7;
            float4 v = *reinterpret_cast<const float4*>(x + (size_t)(m0 + r) * NEMB + k0 + c4 * 4);
            *reinterpret_cast<float4*>(&xs[r][c4 * 4]) = v;
        }
        // W tile 32x128 = 1024 float4
#pragma unroll
        for (int i = 0; i < 4; i++) {
            int idx = tid + i * 256;
            int r = idx >> 5, c4 = idx & 31;
            float4 v = *reinterpret_cast<const float4*>(Wp + (size_t)(k0 + r) * HD + c4 * 4);
            *reinterpret_cast<float4*>(&ws[r][c4 * 4]) = v;
        }
        __syncthreads();

#pragma unroll 8
        for (int kk = 0; kk < PBK; kk++) {
            int kkp = (kk + tx) & (PBK - 1);   // per-thread rotation: bank spread
            float a[4];
#pragma unroll
            for (int i = 0; i < 4; i++) a[i] = xs[ty * 4 + i][kkp];
            float4 b0 = *reinterpret_cast<const float4*>(&ws[kkp][tx * 8]);
            float4 b1 = *reinterpret_cast<const float4*>(&ws[kkp][tx * 8 + 4]);
            float b[8] = {b0.x, b0.y, b0.z, b0.w, b1.x, b1.y, b1.z, b1.w};
#pragma unroll
            for (int i = 0; i < 4; i++)
#pragma unroll
                for (int j = 0; j < 8; j++) acc[i][j] += a[i] * b[j];
        }
        __syncthreads();
    }

#pragma unroll
    for (int i = 0; i < 4; i++) {
        size_t r = (size_t)(m0 + ty * 4 + i);
#pragma unroll
        for (int j = 0; j < 8; j += 4) {
            float4 v = make_float4(acc[i][j], acc[i][j + 1], acc[i][j + 2], acc[i][j + 3]);
            *reinterpret_cast<float4*>(outp + r * HD + tx * 8 + j) = v;
        }
    }
}

// ---------------------------------------------------------------------------
// Flash attention, causal. BM=BN=64, H=128, 256 threads (16x16).
// K and V share one smem buffer (V loaded after S).  exp2-domain softmax.
// ---------------------------------------------------------------------------
#define QS_STRIDE 132
#define PS_STRIDE 65
#define Q_OFF  0
#define KV_OFF (BM * QS_STRIDE)
#define P_OFF  (2 * BM * QS_STRIDE)
#define ATTN_SMEM_FLOATS (2 * BM * QS_STRIDE + BM * PS_STRIDE)
#define ATTN_SMEM_BYTES  (ATTN_SMEM_FLOATS * 4)

__global__ __launch_bounds__(256, 2) void attn_kernel(float* __restrict__ out)
{
    extern __shared__ float sm[];
    float* Qs  = sm + Q_OFF;    // [64][132]
    float* KVs = sm + KV_OFF;   // [64][132]
    float* Ps  = sm + P_OFF;    // [64][65]

    const int b  = blockIdx.y;
    const int bx = blockIdx.x;
    // heavy/light pairing against causal skew
    const int ib = (bx & 1) ? (SEQ / BM - 1 - (bx >> 1)) : (bx >> 1);
    const int q0 = ib * BM;
    const int tid = threadIdx.x;
    const int tx = tid & 15, ty = tid >> 4;

    const float sc = 0.03125f * 1.44269504088896340736f; // (1/sqrt(1024)) * log2(e)

    const float* __restrict__ qg = g_q + ((size_t)b * SEQ + q0) * HD;
#pragma unroll
    for (int i = 0; i < 8; i++) {
        int idx = tid + i * 256;
        int r = idx >> 5, c4 = idx & 31;
        float4 v = *reinterpret_cast<const float4*>(qg + (size_t)r * HD + c4 * 4);
        v.x *= sc; v.y *= sc; v.z *= sc; v.w *= sc;
        *reinterpret_cast<float4*>(Qs + r * QS_STRIDE + c4 * 4) = v;
    }

    float o[4][8], m[4], l[4];
#pragma unroll
    for (int i = 0; i < 4; i++) {
        m[i] = -1e30f; l[i] = 0.f;
#pragma unroll
        for (int j = 0; j < 8; j++) o[i][j] = 0.f;
    }

    for (int jb = 0; jb <= ib; jb++) {
        __syncthreads();  // Qs ready (first iter) / prev V reads done
        const float* __restrict__ kg = g_k + ((size_t)b * SEQ + (size_t)jb * BN) * HD;
#pragma unroll
        for (int i = 0; i < 8; i++) {
            int idx = tid + i * 256;
            int r = idx >> 5, c4 = idx & 31;
            *reinterpret_cast<float4*>(KVs + r * QS_STRIDE + c4 * 4) =
                *reinterpret_cast<const float4*>(kg + (size_t)r * HD + c4 * 4);
        }
        __syncthreads();

        // ---- S = Q * K^T (4x4 per thread), per-thread kk rotation ----
        float s[4][4];
#pragma unroll
        for (int i = 0; i < 4; i++)
#pragma unroll
            for (int j = 0; j < 4; j++) s[i][j] = 0.f;

        const float* qr = Qs  + (ty * 4) * QS_STRIDE;
        const float* kr = KVs + (tx * 4) * QS_STRIDE;
#pragma unroll 8
        for (int kk = 0; kk < HD; kk++) {
            int kkp = (kk + 2 * tx) & (HD - 1);
            float a0 = qr[kkp];
            float a1 = qr[QS_STRIDE + kkp];
            float a2 = qr[2 * QS_STRIDE + kkp];
            float a3 = qr[3 * QS_STRIDE + kkp];
            float c0 = kr[kkp];
            float c1 = kr[QS_STRIDE + kkp];
            float c2 = kr[2 * QS_STRIDE + kkp];
            float c3 = kr[3 * QS_STRIDE + kkp];
            s[0][0] += a0 * c0; s[0][1] += a0 * c1; s[0][2] += a0 * c2; s[0][3] += a0 * c3;
            s[1][0] += a1 * c0; s[1][1] += a1 * c1; s[1][2] += a1 * c2; s[1][3] += a1 * c3;
            s[2][0] += a2 * c0; s[2][1] += a2 * c1; s[2][2] += a2 * c2; s[2][3] += a2 * c3;
            s[3][0] += a3 * c0; s[3][1] += a3 * c1; s[3][2] += a3 * c2; s[3][3] += a3 * c3;
        }

        if (jb == ib) {
#pragma unroll
            for (int i = 0; i < 4; i++) {
                int r = ty * 4 + i;
#pragma unroll
                for (int j = 0; j < 4; j++)
                    if (tx * 4 + j > r) s[i][j] = -1e30f;
            }
        }

        // ---- online softmax (row reduce over 16 tx threads) ----
#pragma unroll
        for (int i = 0; i < 4; i++) {
            float mx = fmaxf(fmaxf(s[i][0], s[i][1]), fmaxf(s[i][2], s[i][3]));
#pragma unroll
            for (int w = 8; w >= 1; w >>= 1)
                mx = fmaxf(mx, __shfl_xor_sync(0xffffffffu, mx, w, 16));
            float mnew  = fmaxf(m[i], mx);
            float alpha = exp2f(m[i] - mnew);
            m[i] = mnew;
            float ls = 0.f;
#pragma unroll
            for (int j = 0; j < 4; j++) {
                float p = exp2f(s[i][j] - mnew);
                s[i][j] = p;
                ls += p;
            }
#pragma unroll
            for (int w = 8; w >= 1; w >>= 1)
                ls += __shfl_xor_sync(0xffffffffu, ls, w, 16);
            l[i] = l[i] * alpha + ls;
#pragma unroll
            for (int j = 0; j < 8; j++) o[i][j] *= alpha;
#pragma unroll
            for (int j = 0; j < 4; j++)
                Ps[(ty * 4 + i) * PS_STRIDE + tx * 4 + j] = s[i][j];
        }
        __syncthreads();  // Ps visible; K reads done -> safe to overwrite KVs

        const float* __restrict__ vg = g_v + ((size_t)b * SEQ + (size_t)jb * BN) * HD;
#pragma unroll
        for (int i = 0; i < 8; i++) {
            int idx = tid + i * 256;
            int r = idx >> 5, c4 = idx & 31;
            *reinterpret_cast<float4*>(KVs + r * QS_STRIDE + c4 * 4) =
                *reinterpret_cast<const float4*>(vg + (size_t)r * HD + c4 * 4);
        }
        __syncthreads();

        // ---- O += P * V (4x8 per thread), per-thread kk rotation ----
        const float* pr = Ps + (ty * 4) * PS_STRIDE;
#pragma unroll 4
        for (int kk = 0; kk < BN; kk++) {
            int kkp = (kk + tx) & (BN - 1);
            float p0 = pr[kkp];
            float p1 = pr[PS_STRIDE + kkp];
            float p2 = pr[2 * PS_STRIDE + kkp];
            float p3 = pr[3 * PS_STRIDE + kkp];
            float4 v0 = *reinterpret_cast<const float4*>(KVs + kkp * QS_STRIDE + tx * 8);
            float4 v1 = *reinterpret_cast<const float4*>(KVs + kkp * QS_STRIDE + tx * 8 + 4);
            float vv[8] = {v0.x, v0.y, v0.z, v0.w, v1.x, v1.y, v1.z, v1.w};
#pragma unroll
            for (int j = 0; j < 8; j++) {
                o[0][j] += p0 * vv[j];
                o[1][j] += p1 * vv[j];
                o[2][j] += p2 * vv[j];
                o[3][j] += p3 * vv[j];
            }
        }
    }

    // ---- epilogue: O /= l ----
    float* __restrict__ og = out + ((size_t)b * SEQ + q0) * HD;
#pragma unroll
    for (int i = 0; i < 4; i++) {
        float inv = 1.f / l[i];
        size_t r = (size_t)(ty * 4 + i);
#pragma unroll
        for (int j = 0; j < 8; j += 4) {
            float4 v = make_float4(o[i][j] * inv, o[i][j + 1] * inv,
                                   o[i][j + 2] * inv, o[i][j + 3] * inv);
            *reinterpret_cast<float4*>(og + r * HD + tx * 8 + j) = v;
        }
    }
}

// ---------------------------------------------------------------------------
extern "C" void kernel_launch(void* const* d_in, const int* in_sizes, int n_in,
                              void* d_out, int out_size)
{
    const float* x  = (const float*)d_in[0];
    const float* Wq = (const float*)d_in[1];
    const float* Wk = (const float*)d_in[2];
    const float* Wv = (const float*)d_in[3];
    float* out = (float*)d_out;

    cudaFuncSetAttribute(attn_kernel, cudaFuncAttributeMaxDynamicSharedMemorySize,
                         ATTN_SMEM_BYTES);

    dim3 pg((BATCH * SEQ) / BM, 3);
    proj_kernel<<<pg, 256>>>(x, Wq, Wk, Wv);

    dim3 ag(SEQ / BM, BATCH);
    attn_kernel<<<ag, 256, ATTN_SMEM_BYTES>>>(out);
}